// round 8
// baseline (speedup 1.0000x reference)
#include <cuda_runtime.h>
#include <cstdint>
#include <math.h>

#define V 30522
#define NBATCH 2
#define SLEN 512
#define DIM 768
#define NJ 12
#define NBK 4
#define NUM_LABELS 7
#define M_TOK (NBATCH*SLEN)   /* 1024 */
#define KDIM (13*DIM)         /* 9984 */
#define GDIM (NJ*DIM)         /* 9216 */
#define NPAIR (NJ*13)         /* 156 */
#define SMALL_MAX 32          /* pairs with cnt<=32 go to the small kernel */

#define ROWP 36
#define STAGE_F ((64+128)*ROWP)           /* big-kernel stage: 6912 floats */
#define SMEM_U_BYTES (3*STAGE_F*4)        /* 82944 */
#define STAGE_S_F ((32+256)*ROWP)         /* small-kernel stage: 10368 floats */
#define SMEM_S_BYTES (2*STAGE_S_F*4)      /* 82944 */

// ---------------- scratch ----------------
__device__ int   g_lp0[V];
__device__ int   g_lp1[V];
__device__ float g_nflat[(size_t)M_TOK*GDIM];     // neighbor sums per (m, j)
__device__ float g_pre[(size_t)M_TOK*GDIM];       // gate accumulator (bias-seeded)
__device__ float g_combined[(size_t)M_TOK*2*DIM]; // [mix | seq]
__device__ float g_final[(size_t)M_TOK*2*DIM];    // [seq | attn_out]
__device__ unsigned int g_amask[M_TOK];
__device__ int   g_pcount[NPAIR];
__device__ int   g_plist[NPAIR*M_TOK];

// ---------------- helpers ----------------
__device__ __forceinline__ uint32_t smem_u32(const void* p) {
    uint32_t a; asm("{ .reg .u64 t; cvta.to.shared.u64 t, %1; cvt.u32.u64 %0, t; }" : "=r"(a) : "l"(p));
    return a;
}
__device__ __forceinline__ void cp16(uint32_t saddr, const void* g) {
    asm volatile("cp.async.ca.shared.global [%0], [%1], 16;" :: "r"(saddr), "l"(g));
}
#define CP_COMMIT() asm volatile("cp.async.commit_group;" ::: "memory")
#define CP_WAIT1()  asm volatile("cp.async.wait_group 1;" ::: "memory")
#define CP_WAIT2()  asm volatile("cp.async.wait_group 2;" ::: "memory")

__device__ __forceinline__ void mma_tf32(float* c, const uint32_t* a, const uint32_t* b) {
    asm volatile("mma.sync.aligned.m16n8k8.row.col.f32.tf32.tf32.f32 "
                 "{%0,%1,%2,%3}, {%4,%5,%6,%7}, {%8,%9}, {%0,%1,%2,%3};"
                 : "+f"(c[0]), "+f"(c[1]), "+f"(c[2]), "+f"(c[3])
                 : "r"(a[0]), "r"(a[1]), "r"(a[2]), "r"(a[3]), "r"(b[0]), "r"(b[1]));
}

// ---------------- small kernels ----------------
__global__ void k_init() {
    int i = blockIdx.x*blockDim.x + threadIdx.x;
    if (i < V) { g_lp0[i] = -1; g_lp1[i] = -1; }
    if (i < NPAIR) g_pcount[i] = 0;
    if (i < M_TOK) g_amask[i] = 0;
}
__global__ void k_scatter2(const int* __restrict__ ids) {
    int* lp = blockIdx.x ? g_lp1 : g_lp0;
    atomicMax(&lp[ids[blockIdx.x*SLEN + threadIdx.x]], (int)threadIdx.x);
}

// Gather neighbor sums + seed g_pre with bias for every active (m, j).
__global__ void k_emb_all(const int* __restrict__ nb, const float* __restrict__ seq,
                          const float* __restrict__ bmlp) {
    int blk = blockIdx.x;             // (b*512+s)*12 + j
    int j = blk % NJ;
    int m = blk / NJ;
    int b = m >> 9;
    const int* nbp = nb + (size_t)blk * NBK;
    int src[4];
    #pragma unroll
    for (int i = 0; i < 4; i++) {
        int id = nbp[i];
        int s0 = g_lp0[id];
        if (b) { int s1 = g_lp1[id]; src[i] = (s1 >= 0) ? (SLEN + s1) : s0; }
        else src[i] = s0;
    }
    if (src[0] < 0 && src[1] < 0 && src[2] < 0 && src[3] < 0) return;
    int t = threadIdx.x;              // 192 threads * float4 = 768
    float4 acc = make_float4(0.f,0.f,0.f,0.f);
    #pragma unroll
    for (int i = 0; i < 4; i++) {
        if (src[i] >= 0) {
            float4 v = ((const float4*)(seq + (size_t)src[i]*DIM))[t];
            acc.x += v.x; acc.y += v.y; acc.z += v.z; acc.w += v.w;
        }
    }
    ((float4*)(g_nflat + (size_t)m*GDIM + (size_t)j*DIM))[t] = acc;
    float4 bv = ((const float4*)(bmlp + (size_t)j*DIM))[t];
    ((float4*)(g_pre + (size_t)m*GDIM + (size_t)j*DIM))[t] = bv;
    if (t == 0) atomicOr(&g_amask[m], 1u << j);
}

__global__ void k_pairs() {
    int m = blockIdx.x*256 + threadIdx.x;
    if (m >= M_TOK) return;
    unsigned mask = g_amask[m];
    if (!mask) return;
    unsigned mm = mask;
    while (mm) {
        int j = __ffs(mm) - 1; mm &= mm - 1;
        int base = j*13;
        int idx = atomicAdd(&g_pcount[base], 1);
        g_plist[base*M_TOK + idx] = m;
        unsigned m2 = mask;
        while (m2) {
            int c = __ffs(m2) - 1; m2 &= m2 - 1;
            int p = base + 1 + c;
            int idx2 = atomicAdd(&g_pcount[p], 1);
            g_plist[p*M_TOK + idx2] = m;
        }
    }
}

// ============ 64x128 mma stage (warps 2m x 4n, frags 2m x 4n) ============
__device__ __forceinline__ void mma_stage64(const uint32_t* sbase, int wm, int wn,
                                            int gid, int tig, float acc[2][4][4]) {
    const uint32_t* As = sbase;
    const uint32_t* Bs = sbase + 64*ROWP;
    #pragma unroll
    for (int ks = 0; ks < 4; ks++) {
        uint32_t a[2][4], b[4][2];
        #pragma unroll
        for (int mt = 0; mt < 2; mt++) {
            int r0 = wm*32 + mt*16 + gid;
            a[mt][0] = As[r0*ROWP + ks*8 + tig];
            a[mt][1] = As[(r0+8)*ROWP + ks*8 + tig];
            a[mt][2] = As[r0*ROWP + ks*8 + tig + 4];
            a[mt][3] = As[(r0+8)*ROWP + ks*8 + tig + 4];
        }
        #pragma unroll
        for (int nt = 0; nt < 4; nt++) {
            int n = wn*32 + nt*8 + gid;
            b[nt][0] = Bs[n*ROWP + ks*8 + tig];
            b[nt][1] = Bs[n*ROWP + ks*8 + tig + 4];
        }
        #pragma unroll
        for (int mt = 0; mt < 2; mt++)
            #pragma unroll
            for (int nt = 0; nt < 4; nt++)
                mma_tf32(acc[mt][nt], a[mt], b[nt]);
    }
}

// ---------------- big pairs (cnt > SMALL_MAX): 64x128, 3-stage ----------------
__global__ __launch_bounds__(256) void k_gemm_big(const float* __restrict__ seq,
                                                  const float* __restrict__ Wmlp) {
    int pid = blockIdx.z;
    int jout = pid / 13, chunk = pid % 13;
    int cnt = g_pcount[pid];
    if (cnt <= SMALL_MAX) return;
    int nbase = blockIdx.y * 128;
    const int* list = g_plist + pid*M_TOK;

    const float* abase = chunk ? (g_nflat + (size_t)(chunk-1)*768) : seq;
    size_t astride = chunk ? (size_t)GDIM : (size_t)DIM;

    extern __shared__ float smem[];
    __shared__ int rows_sh[64];
    uint32_t sb = smem_u32(smem);
    int tid = threadIdx.x;
    int wid = tid >> 5, lane = tid & 31;
    int gid = lane >> 2, tig = lane & 3;
    int wm = wid & 1, wn = wid >> 1;

    const float* bptr[4];
    uint32_t sbb[4];
    #pragma unroll
    for (int i = 0; i < 4; i++) {
        int idx = i*256 + tid;
        int row = idx >> 3, seg = idx & 7;
        bptr[i] = Wmlp + (size_t)(jout*768 + nbase + row)*KDIM + chunk*768 + seg*4;
        sbb[i] = sb + ((64*ROWP) + row*ROWP + seg*4)*4;
    }
    int arow_l[2]; int aseg[2]; uint32_t sa[2];
    #pragma unroll
    for (int i = 0; i < 2; i++) {
        int idx = i*256 + tid;
        arow_l[i] = idx >> 3; aseg[i] = idx & 7;
        sa[i] = sb + (arow_l[i]*ROWP + aseg[i]*4)*4;
    }

    const int NS = 24;
    for (int mt0 = blockIdx.x; mt0*64 < cnt; mt0 += gridDim.x) {
        int m0 = mt0*64;
        __syncthreads();
        if (tid < 64) {
            int mi = m0 + tid;
            rows_sh[tid] = (mi < cnt) ? list[mi] : -1;
        }
        __syncthreads();

        const float* aptr[2];
        #pragma unroll
        for (int i = 0; i < 2; i++) {
            int arow = rows_sh[arow_l[i]];
            aptr[i] = abase + (size_t)(arow < 0 ? 0 : arow)*astride + aseg[i]*4;
        }

        #pragma unroll
        for (int s = 0; s < 3; s++) {
            uint32_t so = s*STAGE_F*4;
            #pragma unroll
            for (int i = 0; i < 2; i++) cp16(sa[i] + so, aptr[i] + s*32);
            #pragma unroll
            for (int i = 0; i < 4; i++) cp16(sbb[i] + so, bptr[i] + s*32);
            CP_COMMIT();
        }

        float acc[2][4][4];
        #pragma unroll
        for (int mt = 0; mt < 2; mt++)
            #pragma unroll
            for (int nt = 0; nt < 4; nt++)
                #pragma unroll
                for (int q = 0; q < 4; q++) acc[mt][nt][q] = 0.f;

        for (int s = 0; s < NS; s++) {
            CP_WAIT2();
            __syncthreads();
            int slot = s % 3;
            mma_stage64((const uint32_t*)smem + slot*STAGE_F, wm, wn, gid, tig, acc);
            __syncthreads();
            if (s + 3 < NS) {
                uint32_t so = slot*STAGE_F*4;
                #pragma unroll
                for (int i = 0; i < 2; i++) cp16(sa[i] + so, aptr[i] + (s + 3)*32);
                #pragma unroll
                for (int i = 0; i < 4; i++) cp16(sbb[i] + so, bptr[i] + (s + 3)*32);
            }
            CP_COMMIT();
        }

        #pragma unroll
        for (int mt = 0; mt < 2; mt++) {
            #pragma unroll
            for (int half = 0; half < 2; half++) {
                int lr = wm*32 + mt*16 + gid + half*8;
                int row = rows_sh[lr];
                if (row < 0) continue;
                float* dst = g_pre + (size_t)row*GDIM + jout*768 + nbase;
                #pragma unroll
                for (int nt = 0; nt < 4; nt++) {
                    int n = wn*32 + nt*8 + 2*tig;
                    atomicAdd(&dst[n],   acc[mt][nt][half*2 + 0]);
                    atomicAdd(&dst[n+1], acc[mt][nt][half*2 + 1]);
                }
            }
        }
    }
}

// ---------------- small pairs (cnt <= SMALL_MAX): 32x256, 2-stage ----------------
__global__ __launch_bounds__(256) void k_gemm_small(const float* __restrict__ seq,
                                                    const float* __restrict__ Wmlp) {
    int pid = blockIdx.z;
    int jout = pid / 13, chunk = pid % 13;
    int cnt = g_pcount[pid];
    if (cnt == 0 || cnt > SMALL_MAX) return;
    int nbase = blockIdx.y * 256;     // 3 n-tiles cover 768
    const int* list = g_plist + pid*M_TOK;

    const float* abase = chunk ? (g_nflat + (size_t)(chunk-1)*768) : seq;
    size_t astride = chunk ? (size_t)GDIM : (size_t)DIM;

    extern __shared__ float smem[];
    __shared__ int rows_sh[32];
    uint32_t sb = smem_u32(smem);
    int tid = threadIdx.x;
    int wid = tid >> 5, lane = tid & 31;
    int gid = lane >> 2, tig = lane & 3;
    // 8 warps along N: warp wid covers cols wid*32..wid*32+31; all warps share the 32 A rows.

    if (tid < 32) rows_sh[tid] = (tid < cnt) ? list[tid] : -1;
    __syncthreads();

    // A: 32 rows x 32 floats = 256 cp16 -> 1 per thread
    int arow_l = tid >> 3, aseg0 = tid & 7;
    int arow = rows_sh[arow_l];
    const float* aptr = abase + (size_t)(arow < 0 ? 0 : arow)*astride + aseg0*4;
    uint32_t sa = sb + (arow_l*ROWP + aseg0*4)*4;
    // B: 256 rows x 32 floats = 2048 cp16 -> 8 per thread
    const float* bptr[8];
    uint32_t sbb[8];
    #pragma unroll
    for (int i = 0; i < 8; i++) {
        int idx = i*256 + tid;
        int row = idx >> 3, seg = idx & 7;
        bptr[i] = Wmlp + (size_t)(jout*768 + nbase + row)*KDIM + chunk*768 + seg*4;
        sbb[i] = sb + ((32*ROWP) + row*ROWP + seg*4)*4;
    }

    const int NS = 24;
    #pragma unroll
    for (int s = 0; s < 2; s++) {
        uint32_t so = s*STAGE_S_F*4;
        cp16(sa + so, aptr + s*32);
        #pragma unroll
        for (int i = 0; i < 8; i++) cp16(sbb[i] + so, bptr[i] + s*32);
        CP_COMMIT();
    }

    float acc[2][4][4];
    #pragma unroll
    for (int mt = 0; mt < 2; mt++)
        #pragma unroll
        for (int nt = 0; nt < 4; nt++)
            #pragma unroll
            for (int q = 0; q < 4; q++) acc[mt][nt][q] = 0.f;

    for (int s = 0; s < NS; s++) {
        CP_WAIT1();
        __syncthreads();
        const uint32_t* As = (const uint32_t*)smem + (s & 1)*STAGE_S_F;
        const uint32_t* Bs = As + 32*ROWP;
        #pragma unroll
        for (int ks = 0; ks < 4; ks++) {
            uint32_t a[2][4], b[4][2];
            #pragma unroll
            for (int mt = 0; mt < 2; mt++) {
                int r0 = mt*16 + gid;
                a[mt][0] = As[r0*ROWP + ks*8 + tig];
                a[mt][1] = As[(r0+8)*ROWP + ks*8 + tig];
                a[mt][2] = As[r0*ROWP + ks*8 + tig + 4];
                a[mt][3] = As[(r0+8)*ROWP + ks*8 + tig + 4];
            }
            #pragma unroll
            for (int nt = 0; nt < 4; nt++) {
                int n = wid*32 + nt*8 + gid;
                b[nt][0] = Bs[n*ROWP + ks*8 + tig];
                b[nt][1] = Bs[n*ROWP + ks*8 + tig + 4];
            }
            #pragma unroll
            for (int mt = 0; mt < 2; mt++)
                #pragma unroll
                for (int nt = 0; nt < 4; nt++)
                    mma_tf32(acc[mt][nt], a[mt], b[nt]);
        }
        __syncthreads();
        if (s + 2 < NS) {
            uint32_t so = (s & 1)*STAGE_S_F*4;
            cp16(sa + so, aptr + (s + 2)*32);
            #pragma unroll
            for (int i = 0; i < 8; i++) cp16(sbb[i] + so, bptr[i] + (s + 2)*32);
        }
        CP_COMMIT();
    }

    #pragma unroll
    for (int mt = 0; mt < 2; mt++) {
        #pragma unroll
        for (int half = 0; half < 2; half++) {
            int lr = mt*16 + gid + half*8;
            int row = rows_sh[lr];
            if (row < 0) continue;
            float* dst = g_pre + (size_t)row*GDIM + jout*768 + nbase;
            #pragma unroll
            for (int nt = 0; nt < 4; nt++) {
                int n = wid*32 + nt*8 + 2*tig;
                atomicAdd(&dst[n],   acc[mt][nt][half*2 + 0]);
                atomicAdd(&dst[n+1], acc[mt][nt][half*2 + 1]);
            }
        }
    }
}

// ---------------- fused gate + attention (j across warps) ----------------
__global__ __launch_bounds__(256) void k_attn2(const float* __restrict__ seq) {
    extern __shared__ float sm[];
    float* sseq = sm;                 // 768
    float* cbuf = sm + DIM;           // 12*768
    __shared__ float sc[NJ], swt[NJ];
    int m = blockIdx.x, t = threadIdx.x;
    int wid = t >> 5, lane = t & 31;
    unsigned mask = g_amask[m];
    for (int d = t; d < DIM; d += 256) sseq[d] = seq[(size_t)m*DIM + d];
    if (t < NJ) sc[t] = 0.f;
    __syncthreads();

    for (int j = wid; j < NJ; j += 8) {
        if (mask & (1u << j)) {
            const float* pre = g_pre + (size_t)m*GDIM + j*768;
            const float* nf  = g_nflat + (size_t)m*GDIM + j*768;
            float part = 0.f;
            for (int d = lane; d < DIM; d += 32) {
                float cv = (1.f / (1.f + expf(-pre[d]))) * nf[d];
                cbuf[j*768 + d] = cv;
                part += cv * sseq[d];
            }
            #pragma unroll
            for (int o = 16; o; o >>= 1) part += __shfl_xor_sync(0xffffffffu, part, o);
            if (lane == 0) sc[j] = part;
        }
    }
    __syncthreads();
    if (t == 0) {
        float mx = sc[0];
        #pragma unroll
        for (int j = 1; j < NJ; j++) mx = fmaxf(mx, sc[j]);
        float sum = 0.f;
        #pragma unroll
        for (int j = 0; j < NJ; j++) { float e = expf(sc[j]-mx); swt[j] = e; sum += e; }
        float inv = 1.f/sum;
        #pragma unroll
        for (int j = 0; j < NJ; j++) swt[j] *= inv;
    }
    __syncthreads();
    for (int d = t; d < DIM; d += 256) {
        float mix = 0.f;
        unsigned m2 = mask;
        while (m2) {
            int j = __ffs(m2) - 1; m2 &= m2 - 1;
            mix += swt[j] * cbuf[j*768 + d];
        }
        g_combined[(size_t)m*2*DIM + d]       = mix;
        g_combined[(size_t)m*2*DIM + DIM + d] = sseq[d];
        g_final[(size_t)m*2*DIM + d]          = sseq[d];
    }
}

// ---------------- attn_out GEMM: tanh(combined @ Wattn^T + b), 64x128, 3-stage ----------------
__global__ __launch_bounds__(256) void k_attnout_mma(const float* __restrict__ Wattn,
                                                     const float* __restrict__ battn) {
    const int KD = 2*DIM;
    int m0 = blockIdx.x * 64;
    int nbase = blockIdx.y * 128;

    extern __shared__ float smem[];
    uint32_t sb = smem_u32(smem);
    int tid = threadIdx.x;
    int wid = tid >> 5, lane = tid & 31;
    int gid = lane >> 2, tig = lane & 3;
    int wm = wid & 1, wn = wid >> 1;

    const float* bptr[4];
    uint32_t sbb[4];
    #pragma unroll
    for (int i = 0; i < 4; i++) {
        int idx = i*256 + tid;
        int row = idx >> 3, seg = idx & 7;
        bptr[i] = Wattn + (size_t)(nbase + row)*KD + seg*4;
        sbb[i] = sb + ((64*ROWP) + row*ROWP + seg*4)*4;
    }
    const float* aptr[2];
    uint32_t sa[2];
    #pragma unroll
    for (int i = 0; i < 2; i++) {
        int idx = i*256 + tid;
        int row = idx >> 3, seg = idx & 7;
        aptr[i] = g_combined + (size_t)(m0 + row)*KD + seg*4;
        sa[i] = sb + (row*ROWP + seg*4)*4;
    }

    const int NS = 48;
    #pragma unroll
    for (int s = 0; s < 3; s++) {
        uint32_t so = s*STAGE_F*4;
        #pragma unroll
        for (int i = 0; i < 2; i++) cp16(sa[i] + so, aptr[i] + s*32);
        #pragma unroll
        for (int i = 0; i < 4; i++) cp16(sbb[i] + so, bptr[i] + s*32);
        CP_COMMIT();
    }

    float acc[2][4][4];
    #pragma unroll
    for (int mt = 0; mt < 2; mt++)
        #pragma unroll
        for (int nt = 0; nt < 4; nt++)
            #pragma unroll
            for (int q = 0; q < 4; q++) acc[mt][nt][q] = 0.f;

    for (int s = 0; s < NS; s++) {
        CP_WAIT2();
        __syncthreads();
        int slot = s % 3;
        mma_stage64((const uint32_t*)smem + slot*STAGE_F, wm, wn, gid, tig, acc);
        __syncthreads();
        if (s + 3 < NS) {
            uint32_t so = slot*STAGE_F*4;
            #pragma unroll
            for (int i = 0; i < 2; i++) cp16(sa[i] + so, aptr[i] + (s + 3)*32);
            #pragma unroll
            for (int i = 0; i < 4; i++) cp16(sbb[i] + so, bptr[i] + (s + 3)*32);
        }
        CP_COMMIT();
    }

    #pragma unroll
    for (int mt = 0; mt < 2; mt++) {
        #pragma unroll
        for (int half = 0; half < 2; half++) {
            int m = m0 + wm*32 + mt*16 + gid + half*8;
            float* dst = g_final + (size_t)m*KD + DIM;
            #pragma unroll
            for (int nt = 0; nt < 4; nt++) {
                int n = nbase + wn*32 + nt*8 + 2*tig;
                dst[n]   = tanhf(acc[mt][nt][half*2 + 0] + battn[n]);
                dst[n+1] = tanhf(acc[mt][nt][half*2 + 1] + battn[n+1]);
            }
        }
    }
}

// ---------------- classification head ----------------
__global__ void k_logits(const float* __restrict__ Wcls, const float* __restrict__ bcls,
                         float* __restrict__ out) {
    int m = blockIdx.x*8 + (threadIdx.x >> 5);
    int lane = threadIdx.x & 31;
    const float* f = g_final + (size_t)m*2*DIM;
    #pragma unroll
    for (int l = 0; l < NUM_LABELS; l++) {
        float p = 0.f;
        const float* wr = Wcls + (size_t)l*2*DIM;
        for (int d = lane; d < 2*DIM; d += 32) p += f[d]*wr[d];
        #pragma unroll
        for (int o = 16; o; o >>= 1) p += __shfl_xor_sync(0xffffffffu, p, o);
        if (lane == 0) out[m*NUM_LABELS + l] = p + bcls[l];
    }
}

// ---------------- launch ----------------
extern "C" void kernel_launch(void* const* d_in, const int* in_sizes, int n_in,
                              void* d_out, int out_size) {
    const float* seq   = (const float*)d_in[0];
    const int*   ids   = (const int*)  d_in[1];
    const int*   nb    = (const int*)  d_in[2];
    const float* Wmlp  = (const float*)d_in[3];
    const float* bmlp  = (const float*)d_in[4];
    const float* Wattn = (const float*)d_in[5];
    const float* battn = (const float*)d_in[6];
    const float* Wcls  = (const float*)d_in[7];
    const float* bcls  = (const float*)d_in[8];
    float* out = (float*)d_out;

    cudaFuncSetAttribute(k_gemm_big,    cudaFuncAttributeMaxDynamicSharedMemorySize, SMEM_U_BYTES);
    cudaFuncSetAttribute(k_gemm_small,  cudaFuncAttributeMaxDynamicSharedMemorySize, SMEM_S_BYTES);
    cudaFuncSetAttribute(k_attnout_mma, cudaFuncAttributeMaxDynamicSharedMemorySize, SMEM_U_BYTES);

    k_init<<<(V+255)/256, 256>>>();
    k_scatter2<<<2, SLEN>>>(ids);
    k_emb_all<<<M_TOK*NJ, 192>>>(nb, seq, bmlp);
    k_pairs<<<(M_TOK+255)/256, 256>>>();
    dim3 gbig(2, 6, NPAIR);
    k_gemm_big<<<gbig, 256, SMEM_U_BYTES>>>(seq, Wmlp);
    dim3 gsml(1, 3, NPAIR);
    k_gemm_small<<<gsml, 256, SMEM_S_BYTES>>>(seq, Wmlp);
    int attn_smem = (DIM + NJ*DIM)*4;
    k_attn2<<<M_TOK, 256, attn_smem>>>(seq);
    dim3 go(M_TOK/64, 6);
    k_attnout_mma<<<go, 256, SMEM_U_BYTES>>>(Wattn, battn);
    k_logits<<<M_TOK/8, 256>>>(Wcls, bcls, out);
}

// round 9
// speedup vs baseline: 1.0663x; 1.0663x over previous
#include <cuda_runtime.h>
#include <cstdint>
#include <math.h>

#define V 30522
#define NBATCH 2
#define SLEN 512
#define DIM 768
#define NJ 12
#define NBK 4
#define NUM_LABELS 7
#define M_TOK (NBATCH*SLEN)   /* 1024 */
#define KDIM (13*DIM)         /* 9984 */
#define GDIM (NJ*DIM)         /* 9216 */
#define NPAIR (NJ*13)         /* 156 */
#define SMALL_MAX 32

#define ROWP 36
#define STAGE_F ((64+128)*ROWP)           /* big path stage: 6912 floats */
#define STAGE_S_F ((32+256)*ROWP)         /* small path stage: 10368 floats */
#define SMEM_U_BYTES (3*STAGE_F*4)        /* 82944 == 2*STAGE_S_F*4 */

// ---------------- scratch ----------------
__device__ int   g_lp0[V];
__device__ int   g_lp1[V];
__device__ float g_nflat[(size_t)M_TOK*GDIM];
__device__ float g_pre[(size_t)M_TOK*GDIM];
__device__ float g_combined[(size_t)M_TOK*2*DIM];
__device__ float g_final[(size_t)M_TOK*2*DIM];
__device__ unsigned int g_amask[M_TOK];
__device__ int   g_pcount[NPAIR];
__device__ int   g_plist[NPAIR*M_TOK];

// ---------------- helpers ----------------
__device__ __forceinline__ uint32_t smem_u32(const void* p) {
    uint32_t a; asm("{ .reg .u64 t; cvta.to.shared.u64 t, %1; cvt.u32.u64 %0, t; }" : "=r"(a) : "l"(p));
    return a;
}
__device__ __forceinline__ void cp16(uint32_t saddr, const void* g) {
    asm volatile("cp.async.ca.shared.global [%0], [%1], 16;" :: "r"(saddr), "l"(g));
}
#define CP_COMMIT() asm volatile("cp.async.commit_group;" ::: "memory")
#define CP_WAIT1()  asm volatile("cp.async.wait_group 1;" ::: "memory")
#define CP_WAIT2()  asm volatile("cp.async.wait_group 2;" ::: "memory")

__device__ __forceinline__ void mma_tf32(float* c, const uint32_t* a, const uint32_t* b) {
    asm volatile("mma.sync.aligned.m16n8k8.row.col.f32.tf32.tf32.f32 "
                 "{%0,%1,%2,%3}, {%4,%5,%6,%7}, {%8,%9}, {%0,%1,%2,%3};"
                 : "+f"(c[0]), "+f"(c[1]), "+f"(c[2]), "+f"(c[3])
                 : "r"(a[0]), "r"(a[1]), "r"(a[2]), "r"(a[3]), "r"(b[0]), "r"(b[1]));
}

// ---------------- small kernels ----------------
__global__ void k_init() {
    int i = blockIdx.x*blockDim.x + threadIdx.x;
    if (i < V) { g_lp0[i] = -1; g_lp1[i] = -1; }
    if (i < M_TOK) g_amask[i] = 0;
}
__global__ void k_scatter2(const int* __restrict__ ids) {
    int* lp = blockIdx.x ? g_lp1 : g_lp0;
    atomicMax(&lp[ids[blockIdx.x*SLEN + threadIdx.x]], (int)threadIdx.x);
}

__global__ void k_emb_all(const int* __restrict__ nb, const float* __restrict__ seq,
                          const float* __restrict__ bmlp) {
    int blk = blockIdx.x;             // (b*512+s)*12 + j
    int j = blk % NJ;
    int m = blk / NJ;
    int b = m >> 9;
    const int* nbp = nb + (size_t)blk * NBK;
    int src[4];
    #pragma unroll
    for (int i = 0; i < 4; i++) {
        int id = nbp[i];
        int s0 = g_lp0[id];
        if (b) { int s1 = g_lp1[id]; src[i] = (s1 >= 0) ? (SLEN + s1) : s0; }
        else src[i] = s0;
    }
    if (src[0] < 0 && src[1] < 0 && src[2] < 0 && src[3] < 0) return;
    int t = threadIdx.x;              // 192 threads * float4 = 768
    float4 acc = make_float4(0.f,0.f,0.f,0.f);
    #pragma unroll
    for (int i = 0; i < 4; i++) {
        if (src[i] >= 0) {
            float4 v = ((const float4*)(seq + (size_t)src[i]*DIM))[t];
            acc.x += v.x; acc.y += v.y; acc.z += v.z; acc.w += v.w;
        }
    }
    ((float4*)(g_nflat + (size_t)m*GDIM + (size_t)j*DIM))[t] = acc;
    float4 bv = ((const float4*)(bmlp + (size_t)j*DIM))[t];
    ((float4*)(g_pre + (size_t)m*GDIM + (size_t)j*DIM))[t] = bv;
    if (t == 0) atomicOr(&g_amask[m], 1u << j);
}

// 156 blocks; each builds its own pair list via ballot compaction. No atomics.
__global__ __launch_bounds__(256) void k_pairs2() {
    int pid = blockIdx.x;
    int j = pid / 13, c = pid % 13;
    int tid = threadIdx.x, lane = tid & 31, wid = tid >> 5;
    __shared__ int wcnt[8];
    int total = 0;
    for (int m0 = 0; m0 < M_TOK; m0 += 256) {
        int m = m0 + tid;
        unsigned mask = g_amask[m];
        bool ok = ((mask >> j) & 1u) && (c == 0 || ((mask >> (c-1)) & 1u));
        unsigned bal = __ballot_sync(0xffffffffu, ok);
        if (lane == 0) wcnt[wid] = __popc(bal);
        __syncthreads();
        int woff = 0, bsum = 0;
        #pragma unroll
        for (int i = 0; i < 8; i++) { if (i < wid) woff += wcnt[i]; bsum += wcnt[i]; }
        if (ok) {
            int pos = total + woff + __popc(bal & ((1u << lane) - 1u));
            g_plist[pid*M_TOK + pos] = m;
        }
        total += bsum;
        __syncthreads();
    }
    if (tid == 0) g_pcount[pid] = total;
}

// ============ 64x128 mma stage (warps 2m x 4n, frags 2m x 4n) ============
__device__ __forceinline__ void mma_stage64(const uint32_t* sbase, int wm, int wn,
                                            int gid, int tig, float acc[2][4][4]) {
    const uint32_t* As = sbase;
    const uint32_t* Bs = sbase + 64*ROWP;
    #pragma unroll
    for (int ks = 0; ks < 4; ks++) {
        uint32_t a[2][4], b[4][2];
        #pragma unroll
        for (int mt = 0; mt < 2; mt++) {
            int r0 = wm*32 + mt*16 + gid;
            a[mt][0] = As[r0*ROWP + ks*8 + tig];
            a[mt][1] = As[(r0+8)*ROWP + ks*8 + tig];
            a[mt][2] = As[r0*ROWP + ks*8 + tig + 4];
            a[mt][3] = As[(r0+8)*ROWP + ks*8 + tig + 4];
        }
        #pragma unroll
        for (int nt = 0; nt < 4; nt++) {
            int n = wn*32 + nt*8 + gid;
            b[nt][0] = Bs[n*ROWP + ks*8 + tig];
            b[nt][1] = Bs[n*ROWP + ks*8 + tig + 4];
        }
        #pragma unroll
        for (int mt = 0; mt < 2; mt++)
            #pragma unroll
            for (int nt = 0; nt < 4; nt++)
                mma_tf32(acc[mt][nt], a[mt], b[nt]);
    }
}

// ---------------- unified size-adaptive sparse GEMM (single launch) ----------------
__global__ __launch_bounds__(256) void k_gemmU2(const float* __restrict__ seq,
                                                const float* __restrict__ Wmlp) {
    int pid = blockIdx.z;
    int jout = pid / 13, chunk = pid % 13;
    int cnt = g_pcount[pid];
    if (cnt == 0) return;
    const int* list = g_plist + pid*M_TOK;
    const float* abase = chunk ? (g_nflat + (size_t)(chunk-1)*768) : seq;
    size_t astride = chunk ? (size_t)GDIM : (size_t)DIM;

    extern __shared__ float smem[];
    __shared__ int rows_sh[64];
    uint32_t sb = smem_u32(smem);
    int tid = threadIdx.x;
    int wid = tid >> 5, lane = tid & 31;
    int gid = lane >> 2, tig = lane & 3;
    const int NS = 24;

    if (cnt <= SMALL_MAX) {
        // ---- 32x256 path: 3 CTAs (x==0, y<3) ----
        if (blockIdx.x != 0 || blockIdx.y >= 3) return;
        int nbase = blockIdx.y * 256;

        if (tid < 32) rows_sh[tid] = (tid < cnt) ? list[tid] : -1;
        __syncthreads();

        int arow_l = tid >> 3, aseg0 = tid & 7;
        int arow = rows_sh[arow_l];
        const float* aptr = abase + (size_t)(arow < 0 ? 0 : arow)*astride + aseg0*4;
        uint32_t sa = sb + (arow_l*ROWP + aseg0*4)*4;
        const float* bptr[8];
        uint32_t sbb[8];
        #pragma unroll
        for (int i = 0; i < 8; i++) {
            int idx = i*256 + tid;
            int row = idx >> 3, seg = idx & 7;
            bptr[i] = Wmlp + (size_t)(jout*768 + nbase + row)*KDIM + chunk*768 + seg*4;
            sbb[i] = sb + ((32*ROWP) + row*ROWP + seg*4)*4;
        }

        #pragma unroll
        for (int s = 0; s < 2; s++) {
            uint32_t so = s*STAGE_S_F*4;
            cp16(sa + so, aptr + s*32);
            #pragma unroll
            for (int i = 0; i < 8; i++) cp16(sbb[i] + so, bptr[i] + s*32);
            CP_COMMIT();
        }

        float acc[2][4][4];
        #pragma unroll
        for (int mt = 0; mt < 2; mt++)
            #pragma unroll
            for (int nt = 0; nt < 4; nt++)
                #pragma unroll
                for (int q = 0; q < 4; q++) acc[mt][nt][q] = 0.f;

        for (int s = 0; s < NS; s++) {
            CP_WAIT1();
            __syncthreads();
            const uint32_t* As = (const uint32_t*)smem + (s & 1)*STAGE_S_F;
            const uint32_t* Bs = As + 32*ROWP;
            #pragma unroll
            for (int ks = 0; ks < 4; ks++) {
                uint32_t a[2][4], b[4][2];
                #pragma unroll
                for (int mt = 0; mt < 2; mt++) {
                    int r0 = mt*16 + gid;
                    a[mt][0] = As[r0*ROWP + ks*8 + tig];
                    a[mt][1] = As[(r0+8)*ROWP + ks*8 + tig];
                    a[mt][2] = As[r0*ROWP + ks*8 + tig + 4];
                    a[mt][3] = As[(r0+8)*ROWP + ks*8 + tig + 4];
                }
                #pragma unroll
                for (int nt = 0; nt < 4; nt++) {
                    int n = wid*32 + nt*8 + gid;
                    b[nt][0] = Bs[n*ROWP + ks*8 + tig];
                    b[nt][1] = Bs[n*ROWP + ks*8 + tig + 4];
                }
                #pragma unroll
                for (int mt = 0; mt < 2; mt++)
                    #pragma unroll
                    for (int nt = 0; nt < 4; nt++)
                        mma_tf32(acc[mt][nt], a[mt], b[nt]);
            }
            __syncthreads();
            if (s + 2 < NS) {
                uint32_t so = (s & 1)*STAGE_S_F*4;
                cp16(sa + so, aptr + (s + 2)*32);
                #pragma unroll
                for (int i = 0; i < 8; i++) cp16(sbb[i] + so, bptr[i] + (s + 2)*32);
            }
            CP_COMMIT();
        }

        #pragma unroll
        for (int mt = 0; mt < 2; mt++) {
            #pragma unroll
            for (int half = 0; half < 2; half++) {
                int lr = mt*16 + gid + half*8;
                int row = rows_sh[lr];
                if (row < 0) continue;
                float* dst = g_pre + (size_t)row*GDIM + jout*768 + nbase;
                #pragma unroll
                for (int nt = 0; nt < 4; nt++) {
                    int n = wid*32 + nt*8 + 2*tig;
                    atomicAdd(&dst[n],   acc[mt][nt][half*2 + 0]);
                    atomicAdd(&dst[n+1], acc[mt][nt][half*2 + 1]);
                }
            }
        }
    } else {
        // ---- 64x128 path, 3-stage, m-stride over blockIdx.x ----
        int nbase = blockIdx.y * 128;
        int wm = wid & 1, wn = wid >> 1;

        const float* bptr[4];
        uint32_t sbb[4];
        #pragma unroll
        for (int i = 0; i < 4; i++) {
            int idx = i*256 + tid;
            int row = idx >> 3, seg = idx & 7;
            bptr[i] = Wmlp + (size_t)(jout*768 + nbase + row)*KDIM + chunk*768 + seg*4;
            sbb[i] = sb + ((64*ROWP) + row*ROWP + seg*4)*4;
        }
        int arow_l[2]; int aseg[2]; uint32_t sa[2];
        #pragma unroll
        for (int i = 0; i < 2; i++) {
            int idx = i*256 + tid;
            arow_l[i] = idx >> 3; aseg[i] = idx & 7;
            sa[i] = sb + (arow_l[i]*ROWP + aseg[i]*4)*4;
        }

        for (int mt0 = blockIdx.x; mt0*64 < cnt; mt0 += gridDim.x) {
            int m0 = mt0*64;
            __syncthreads();
            if (tid < 64) {
                int mi = m0 + tid;
                rows_sh[tid] = (mi < cnt) ? list[mi] : -1;
            }
            __syncthreads();

            const float* aptr[2];
            #pragma unroll
            for (int i = 0; i < 2; i++) {
                int arow = rows_sh[arow_l[i]];
                aptr[i] = abase + (size_t)(arow < 0 ? 0 : arow)*astride + aseg[i]*4;
            }

            #pragma unroll
            for (int s = 0; s < 3; s++) {
                uint32_t so = s*STAGE_F*4;
                #pragma unroll
                for (int i = 0; i < 2; i++) cp16(sa[i] + so, aptr[i] + s*32);
                #pragma unroll
                for (int i = 0; i < 4; i++) cp16(sbb[i] + so, bptr[i] + s*32);
                CP_COMMIT();
            }

            float acc[2][4][4];
            #pragma unroll
            for (int mt = 0; mt < 2; mt++)
                #pragma unroll
                for (int nt = 0; nt < 4; nt++)
                    #pragma unroll
                    for (int q = 0; q < 4; q++) acc[mt][nt][q] = 0.f;

            for (int s = 0; s < NS; s++) {
                CP_WAIT2();
                __syncthreads();
                int slot = s % 3;
                mma_stage64((const uint32_t*)smem + slot*STAGE_F, wm, wn, gid, tig, acc);
                __syncthreads();
                if (s + 3 < NS) {
                    uint32_t so = slot*STAGE_F*4;
                    #pragma unroll
                    for (int i = 0; i < 2; i++) cp16(sa[i] + so, aptr[i] + (s + 3)*32);
                    #pragma unroll
                    for (int i = 0; i < 4; i++) cp16(sbb[i] + so, bptr[i] + (s + 3)*32);
                }
                CP_COMMIT();
            }

            #pragma unroll
            for (int mt = 0; mt < 2; mt++) {
                #pragma unroll
                for (int half = 0; half < 2; half++) {
                    int lr = wm*32 + mt*16 + gid + half*8;
                    int row = rows_sh[lr];
                    if (row < 0) continue;
                    float* dst = g_pre + (size_t)row*GDIM + jout*768 + nbase;
                    #pragma unroll
                    for (int nt = 0; nt < 4; nt++) {
                        int n = wn*32 + nt*8 + 2*tig;
                        atomicAdd(&dst[n],   acc[mt][nt][half*2 + 0]);
                        atomicAdd(&dst[n+1], acc[mt][nt][half*2 + 1]);
                    }
                }
            }
        }
    }
}

// ---------------- fused gate + attention (j across warps) ----------------
__global__ __launch_bounds__(256) void k_attn2(const float* __restrict__ seq) {
    extern __shared__ float sm[];
    float* sseq = sm;
    float* cbuf = sm + DIM;
    __shared__ float sc[NJ], swt[NJ];
    int m = blockIdx.x, t = threadIdx.x;
    int wid = t >> 5, lane = t & 31;
    unsigned mask = g_amask[m];
    for (int d = t; d < DIM; d += 256) sseq[d] = seq[(size_t)m*DIM + d];
    if (t < NJ) sc[t] = 0.f;
    __syncthreads();

    for (int j = wid; j < NJ; j += 8) {
        if (mask & (1u << j)) {
            const float* pre = g_pre + (size_t)m*GDIM + j*768;
            const float* nf  = g_nflat + (size_t)m*GDIM + j*768;
            float part = 0.f;
            for (int d = lane; d < DIM; d += 32) {
                float cv = (1.f / (1.f + expf(-pre[d]))) * nf[d];
                cbuf[j*768 + d] = cv;
                part += cv * sseq[d];
            }
            #pragma unroll
            for (int o = 16; o; o >>= 1) part += __shfl_xor_sync(0xffffffffu, part, o);
            if (lane == 0) sc[j] = part;
        }
    }
    __syncthreads();
    if (t == 0) {
        float mx = sc[0];
        #pragma unroll
        for (int j = 1; j < NJ; j++) mx = fmaxf(mx, sc[j]);
        float sum = 0.f;
        #pragma unroll
        for (int j = 0; j < NJ; j++) { float e = expf(sc[j]-mx); swt[j] = e; sum += e; }
        float inv = 1.f/sum;
        #pragma unroll
        for (int j = 0; j < NJ; j++) swt[j] *= inv;
    }
    __syncthreads();
    for (int d = t; d < DIM; d += 256) {
        float mix = 0.f;
        unsigned m2 = mask;
        while (m2) {
            int j = __ffs(m2) - 1; m2 &= m2 - 1;
            mix += swt[j] * cbuf[j*768 + d];
        }
        g_combined[(size_t)m*2*DIM + d]       = mix;
        g_combined[(size_t)m*2*DIM + DIM + d] = sseq[d];
        g_final[(size_t)m*2*DIM + d]          = sseq[d];
    }
}

// ---------------- attn_out GEMM: tanh(combined @ Wattn^T + b), 64x128, 3-stage ----------------
__global__ __launch_bounds__(256) void k_attnout_mma(const float* __restrict__ Wattn,
                                                     const float* __restrict__ battn) {
    const int KD = 2*DIM;
    int m0 = blockIdx.x * 64;
    int nbase = blockIdx.y * 128;

    extern __shared__ float smem[];
    uint32_t sb = smem_u32(smem);
    int tid = threadIdx.x;
    int wid = tid >> 5, lane = tid & 31;
    int gid = lane >> 2, tig = lane & 3;
    int wm = wid & 1, wn = wid >> 1;

    const float* bptr[4];
    uint32_t sbb[4];
    #pragma unroll
    for (int i = 0; i < 4; i++) {
        int idx = i*256 + tid;
        int row = idx >> 3, seg = idx & 7;
        bptr[i] = Wattn + (size_t)(nbase + row)*KD + seg*4;
        sbb[i] = sb + ((64*ROWP) + row*ROWP + seg*4)*4;
    }
    const float* aptr[2];
    uint32_t sa[2];
    #pragma unroll
    for (int i = 0; i < 2; i++) {
        int idx = i*256 + tid;
        int row = idx >> 3, seg = idx & 7;
        aptr[i] = g_combined + (size_t)(m0 + row)*KD + seg*4;
        sa[i] = sb + (row*ROWP + seg*4)*4;
    }

    const int NS = 48;
    #pragma unroll
    for (int s = 0; s < 3; s++) {
        uint32_t so = s*STAGE_F*4;
        #pragma unroll
        for (int i = 0; i < 2; i++) cp16(sa[i] + so, aptr[i] + s*32);
        #pragma unroll
        for (int i = 0; i < 4; i++) cp16(sbb[i] + so, bptr[i] + s*32);
        CP_COMMIT();
    }

    float acc[2][4][4];
    #pragma unroll
    for (int mt = 0; mt < 2; mt++)
        #pragma unroll
        for (int nt = 0; nt < 4; nt++)
            #pragma unroll
            for (int q = 0; q < 4; q++) acc[mt][nt][q] = 0.f;

    for (int s = 0; s < NS; s++) {
        CP_WAIT2();
        __syncthreads();
        int slot = s % 3;
        mma_stage64((const uint32_t*)smem + slot*STAGE_F, wm, wn, gid, tig, acc);
        __syncthreads();
        if (s + 3 < NS) {
            uint32_t so = slot*STAGE_F*4;
            #pragma unroll
            for (int i = 0; i < 2; i++) cp16(sa[i] + so, aptr[i] + (s + 3)*32);
            #pragma unroll
            for (int i = 0; i < 4; i++) cp16(sbb[i] + so, bptr[i] + (s + 3)*32);
        }
        CP_COMMIT();
    }

    #pragma unroll
    for (int mt = 0; mt < 2; mt++) {
        #pragma unroll
        for (int half = 0; half < 2; half++) {
            int m = m0 + wm*32 + mt*16 + gid + half*8;
            float* dst = g_final + (size_t)m*KD + DIM;
            #pragma unroll
            for (int nt = 0; nt < 4; nt++) {
                int n = nbase + wn*32 + nt*8 + 2*tig;
                dst[n]   = tanhf(acc[mt][nt][half*2 + 0] + battn[n]);
                dst[n+1] = tanhf(acc[mt][nt][half*2 + 1] + battn[n+1]);
            }
        }
    }
}

// ---------------- classification head ----------------
__global__ void k_logits(const float* __restrict__ Wcls, const float* __restrict__ bcls,
                         float* __restrict__ out) {
    int m = blockIdx.x*8 + (threadIdx.x >> 5);
    int lane = threadIdx.x & 31;
    const float* f = g_final + (size_t)m*2*DIM;
    #pragma unroll
    for (int l = 0; l < NUM_LABELS; l++) {
        float p = 0.f;
        const float* wr = Wcls + (size_t)l*2*DIM;
        for (int d = lane; d < 2*DIM; d += 32) p += f[d]*wr[d];
        #pragma unroll
        for (int o = 16; o; o >>= 1) p += __shfl_xor_sync(0xffffffffu, p, o);
        if (lane == 0) out[m*NUM_LABELS + l] = p + bcls[l];
    }
}

// ---------------- launch ----------------
extern "C" void kernel_launch(void* const* d_in, const int* in_sizes, int n_in,
                              void* d_out, int out_size) {
    const float* seq   = (const float*)d_in[0];
    const int*   ids   = (const int*)  d_in[1];
    const int*   nb    = (const int*)  d_in[2];
    const float* Wmlp  = (const float*)d_in[3];
    const float* bmlp  = (const float*)d_in[4];
    const float* Wattn = (const float*)d_in[5];
    const float* battn = (const float*)d_in[6];
    const float* Wcls  = (const float*)d_in[7];
    const float* bcls  = (const float*)d_in[8];
    float* out = (float*)d_out;

    cudaFuncSetAttribute(k_gemmU2,      cudaFuncAttributeMaxDynamicSharedMemorySize, SMEM_U_BYTES);
    cudaFuncSetAttribute(k_attnout_mma, cudaFuncAttributeMaxDynamicSharedMemorySize, SMEM_U_BYTES);

    k_init<<<(V+255)/256, 256>>>();
    k_scatter2<<<2, SLEN>>>(ids);
    k_emb_all<<<M_TOK*NJ, 192>>>(nb, seq, bmlp);
    k_pairs2<<<NPAIR, 256>>>();
    dim3 gu(2, 6, NPAIR);             // one launch; size-adaptive tiles inside
    k_gemmU2<<<gu, 256, SMEM_U_BYTES>>>(seq, Wmlp);
    int attn_smem = (DIM + NJ*DIM)*4;
    k_attn2<<<M_TOK, 256, attn_smem>>>(seq);
    dim3 go(M_TOK/64, 6);
    k_attnout_mma<<<go, 256, SMEM_U_BYTES>>>(Wattn, battn);
    k_logits<<<M_TOK/8, 256>>>(Wcls, bcls, out);
}

// round 10
// speedup vs baseline: 1.1570x; 1.0851x over previous
#include <cuda_runtime.h>
#include <cstdint>
#include <math.h>

#define V 30522
#define NBATCH 2
#define SLEN 512
#define DIM 768
#define NJ 12
#define NBK 4
#define NUM_LABELS 7
#define M_TOK (NBATCH*SLEN)   /* 1024 */
#define KDIM (13*DIM)         /* 9984 */
#define GDIM (NJ*DIM)         /* 9216 */
#define NPAIR (NJ*13)         /* 156 */
#define SMALL_MAX 32

#define ROWP 36
#define STAGE_F ((64+128)*ROWP)           /* big path stage: 6912 floats */
#define STAGE_S_F ((32+128)*ROWP)         /* small path stage: 5760 floats */
#define SMEM_U_BYTES (3*STAGE_F*4)        /* 82944 */

// ---------------- scratch ----------------
__device__ int   g_lp0[V];
__device__ int   g_lp1[V];
__device__ float g_nflat[(size_t)M_TOK*GDIM];
__device__ float g_pre[(size_t)M_TOK*GDIM];
__device__ float g_combined[(size_t)M_TOK*2*DIM];
__device__ unsigned int g_amask[M_TOK];
__device__ int   g_pcount[NPAIR];
__device__ int   g_plist[NPAIR*M_TOK];

// ---------------- helpers ----------------
__device__ __forceinline__ uint32_t smem_u32(const void* p) {
    uint32_t a; asm("{ .reg .u64 t; cvta.to.shared.u64 t, %1; cvt.u32.u64 %0, t; }" : "=r"(a) : "l"(p));
    return a;
}
__device__ __forceinline__ void cp16(uint32_t saddr, const void* g) {
    asm volatile("cp.async.ca.shared.global [%0], [%1], 16;" :: "r"(saddr), "l"(g));
}
#define CP_COMMIT() asm volatile("cp.async.commit_group;" ::: "memory")
#define CP_WAIT2()  asm volatile("cp.async.wait_group 2;" ::: "memory")

__device__ __forceinline__ void mma_tf32(float* c, const uint32_t* a, const uint32_t* b) {
    asm volatile("mma.sync.aligned.m16n8k8.row.col.f32.tf32.tf32.f32 "
                 "{%0,%1,%2,%3}, {%4,%5,%6,%7}, {%8,%9}, {%0,%1,%2,%3};"
                 : "+f"(c[0]), "+f"(c[1]), "+f"(c[2]), "+f"(c[3])
                 : "r"(a[0]), "r"(a[1]), "r"(a[2]), "r"(a[3]), "r"(b[0]), "r"(b[1]));
}

// ---------------- small kernels ----------------
__global__ void k_init() {
    int i = blockIdx.x*blockDim.x + threadIdx.x;
    if (i < V) { g_lp0[i] = -1; g_lp1[i] = -1; }
    if (i < M_TOK) g_amask[i] = 0;
}
__global__ void k_scatter2(const int* __restrict__ ids) {
    int* lp = blockIdx.x ? g_lp1 : g_lp0;
    atomicMax(&lp[ids[blockIdx.x*SLEN + threadIdx.x]], (int)threadIdx.x);
}

__global__ void k_emb_all(const int* __restrict__ nb, const float* __restrict__ seq,
                          const float* __restrict__ bmlp) {
    int blk = blockIdx.x;             // (b*512+s)*12 + j
    int j = blk % NJ;
    int m = blk / NJ;
    int b = m >> 9;
    const int* nbp = nb + (size_t)blk * NBK;
    int src[4];
    #pragma unroll
    for (int i = 0; i < 4; i++) {
        int id = nbp[i];
        int s0 = g_lp0[id];
        if (b) { int s1 = g_lp1[id]; src[i] = (s1 >= 0) ? (SLEN + s1) : s0; }
        else src[i] = s0;
    }
    if (src[0] < 0 && src[1] < 0 && src[2] < 0 && src[3] < 0) return;
    int t = threadIdx.x;              // 192 threads * float4 = 768
    float4 acc = make_float4(0.f,0.f,0.f,0.f);
    #pragma unroll
    for (int i = 0; i < 4; i++) {
        if (src[i] >= 0) {
            float4 v = ((const float4*)(seq + (size_t)src[i]*DIM))[t];
            acc.x += v.x; acc.y += v.y; acc.z += v.z; acc.w += v.w;
        }
    }
    ((float4*)(g_nflat + (size_t)m*GDIM + (size_t)j*DIM))[t] = acc;
    float4 bv = ((const float4*)(bmlp + (size_t)j*DIM))[t];
    ((float4*)(g_pre + (size_t)m*GDIM + (size_t)j*DIM))[t] = bv;
    if (t == 0) atomicOr(&g_amask[m], 1u << j);
}

// 156 blocks; ballot compaction, no atomics.
__global__ __launch_bounds__(256) void k_pairs2() {
    int pid = blockIdx.x;
    int j = pid / 13, c = pid % 13;
    int tid = threadIdx.x, lane = tid & 31, wid = tid >> 5;
    __shared__ int wcnt[8];
    int total = 0;
    for (int m0 = 0; m0 < M_TOK; m0 += 256) {
        int m = m0 + tid;
        unsigned mask = g_amask[m];
        bool ok = ((mask >> j) & 1u) && (c == 0 || ((mask >> (c-1)) & 1u));
        unsigned bal = __ballot_sync(0xffffffffu, ok);
        if (lane == 0) wcnt[wid] = __popc(bal);
        __syncthreads();
        int woff = 0, bsum = 0;
        #pragma unroll
        for (int i = 0; i < 8; i++) { if (i < wid) woff += wcnt[i]; bsum += wcnt[i]; }
        if (ok) {
            int pos = total + woff + __popc(bal & ((1u << lane) - 1u));
            g_plist[pid*M_TOK + pos] = m;
        }
        total += bsum;
        __syncthreads();
    }
    if (tid == 0) g_pcount[pid] = total;
}

// ============ 64x128 mma stage (warps 2m x 4n, frags 2m x 4n) ============
__device__ __forceinline__ void mma_stage64(const uint32_t* sbase, int wm, int wn,
                                            int gid, int tig, float acc[2][4][4]) {
    const uint32_t* As = sbase;
    const uint32_t* Bs = sbase + 64*ROWP;
    #pragma unroll
    for (int ks = 0; ks < 4; ks++) {
        uint32_t a[2][4], b[4][2];
        #pragma unroll
        for (int mt = 0; mt < 2; mt++) {
            int r0 = wm*32 + mt*16 + gid;
            a[mt][0] = As[r0*ROWP + ks*8 + tig];
            a[mt][1] = As[(r0+8)*ROWP + ks*8 + tig];
            a[mt][2] = As[r0*ROWP + ks*8 + tig + 4];
            a[mt][3] = As[(r0+8)*ROWP + ks*8 + tig + 4];
        }
        #pragma unroll
        for (int nt = 0; nt < 4; nt++) {
            int n = wn*32 + nt*8 + gid;
            b[nt][0] = Bs[n*ROWP + ks*8 + tig];
            b[nt][1] = Bs[n*ROWP + ks*8 + tig + 4];
        }
        #pragma unroll
        for (int mt = 0; mt < 2; mt++)
            #pragma unroll
            for (int nt = 0; nt < 4; nt++)
                mma_tf32(acc[mt][nt], a[mt], b[nt]);
    }
}

// ============ 32x128 mma stage (warps 2m x 4n, 16 rows/warp) ============
__device__ __forceinline__ void mma_stage32(const uint32_t* sbase, int wm, int wn,
                                            int gid, int tig, float acc[4][4]) {
    const uint32_t* As = sbase;
    const uint32_t* Bs = sbase + 32*ROWP;
    #pragma unroll
    for (int ks = 0; ks < 4; ks++) {
        uint32_t a[4], b[4][2];
        int r0 = wm*16 + gid;
        a[0] = As[r0*ROWP + ks*8 + tig];
        a[1] = As[(r0+8)*ROWP + ks*8 + tig];
        a[2] = As[r0*ROWP + ks*8 + tig + 4];
        a[3] = As[(r0+8)*ROWP + ks*8 + tig + 4];
        #pragma unroll
        for (int nt = 0; nt < 4; nt++) {
            int n = wn*32 + nt*8 + gid;
            b[nt][0] = Bs[n*ROWP + ks*8 + tig];
            b[nt][1] = Bs[n*ROWP + ks*8 + tig + 4];
        }
        #pragma unroll
        for (int nt = 0; nt < 4; nt++)
            mma_tf32(acc[nt], a, b[nt]);
    }
}

// ---------------- unified size-adaptive sparse GEMM (single launch, grid 3x6x156) ----------------
__global__ __launch_bounds__(256) void k_gemmU2(const float* __restrict__ seq,
                                                const float* __restrict__ Wmlp) {
    int pid = blockIdx.z;
    int jout = pid / 13, chunk = pid % 13;
    int cnt = g_pcount[pid];
    if (cnt == 0) return;
    const int* list = g_plist + pid*M_TOK;
    const float* abase = chunk ? (g_nflat + (size_t)(chunk-1)*768) : seq;
    size_t astride = chunk ? (size_t)GDIM : (size_t)DIM;
    int nbase = blockIdx.y * 128;

    extern __shared__ float smem[];
    __shared__ int rows_sh[64];
    uint32_t sb = smem_u32(smem);
    int tid = threadIdx.x;
    int wid = tid >> 5, lane = tid & 31;
    int gid = lane >> 2, tig = lane & 3;
    const int NS = 24;

    if (cnt <= SMALL_MAX) {
        // ---- 32x128 path, 3-stage: 6 CTAs (x==0) ----
        if (blockIdx.x != 0) return;
        int wm = wid & 1, wn = wid >> 1;

        if (tid < 32) rows_sh[tid] = (tid < cnt) ? list[tid] : -1;
        __syncthreads();

        int arow_l = tid >> 3, aseg0 = tid & 7;
        int arow = rows_sh[arow_l];
        const float* aptr = abase + (size_t)(arow < 0 ? 0 : arow)*astride + aseg0*4;
        uint32_t sa = sb + (arow_l*ROWP + aseg0*4)*4;
        const float* bptr[4];
        uint32_t sbb[4];
        #pragma unroll
        for (int i = 0; i < 4; i++) {
            int idx = i*256 + tid;
            int row = idx >> 3, seg = idx & 7;
            bptr[i] = Wmlp + (size_t)(jout*768 + nbase + row)*KDIM + chunk*768 + seg*4;
            sbb[i] = sb + ((32*ROWP) + row*ROWP + seg*4)*4;
        }

        #pragma unroll
        for (int s = 0; s < 3; s++) {
            uint32_t so = s*STAGE_S_F*4;
            cp16(sa + so, aptr + s*32);
            #pragma unroll
            for (int i = 0; i < 4; i++) cp16(sbb[i] + so, bptr[i] + s*32);
            CP_COMMIT();
        }

        float acc[4][4];
        #pragma unroll
        for (int nt = 0; nt < 4; nt++)
            #pragma unroll
            for (int q = 0; q < 4; q++) acc[nt][q] = 0.f;

        for (int s = 0; s < NS; s++) {
            CP_WAIT2();
            __syncthreads();
            int slot = s % 3;
            mma_stage32((const uint32_t*)smem + slot*STAGE_S_F, wm, wn, gid, tig, acc);
            __syncthreads();
            if (s + 3 < NS) {
                uint32_t so = slot*STAGE_S_F*4;
                cp16(sa + so, aptr + (s + 3)*32);
                #pragma unroll
                for (int i = 0; i < 4; i++) cp16(sbb[i] + so, bptr[i] + (s + 3)*32);
            }
            CP_COMMIT();
        }

        #pragma unroll
        for (int half = 0; half < 2; half++) {
            int lr = wm*16 + gid + half*8;
            int row = rows_sh[lr];
            if (row < 0) continue;
            float* dst = g_pre + (size_t)row*GDIM + jout*768 + nbase;
            #pragma unroll
            for (int nt = 0; nt < 4; nt++) {
                int n = wn*32 + nt*8 + 2*tig;
                atomicAdd(&dst[n],   acc[nt][half*2 + 0]);
                atomicAdd(&dst[n+1], acc[nt][half*2 + 1]);
            }
        }
    } else {
        // ---- 64x128 path, 3-stage; gridDim.x=3 covers all m-tiles concurrently ----
        int wm = wid & 1, wn = wid >> 1;

        const float* bptr[4];
        uint32_t sbb[4];
        #pragma unroll
        for (int i = 0; i < 4; i++) {
            int idx = i*256 + tid;
            int row = idx >> 3, seg = idx & 7;
            bptr[i] = Wmlp + (size_t)(jout*768 + nbase + row)*KDIM + chunk*768 + seg*4;
            sbb[i] = sb + ((64*ROWP) + row*ROWP + seg*4)*4;
        }
        int arow_l[2]; int aseg[2]; uint32_t sa[2];
        #pragma unroll
        for (int i = 0; i < 2; i++) {
            int idx = i*256 + tid;
            arow_l[i] = idx >> 3; aseg[i] = idx & 7;
            sa[i] = sb + (arow_l[i]*ROWP + aseg[i]*4)*4;
        }

        for (int mt0 = blockIdx.x; mt0*64 < cnt; mt0 += gridDim.x) {
            int m0 = mt0*64;
            __syncthreads();
            if (tid < 64) {
                int mi = m0 + tid;
                rows_sh[tid] = (mi < cnt) ? list[mi] : -1;
            }
            __syncthreads();

            const float* aptr[2];
            #pragma unroll
            for (int i = 0; i < 2; i++) {
                int arow = rows_sh[arow_l[i]];
                aptr[i] = abase + (size_t)(arow < 0 ? 0 : arow)*astride + aseg[i]*4;
            }

            #pragma unroll
            for (int s = 0; s < 3; s++) {
                uint32_t so = s*STAGE_F*4;
                #pragma unroll
                for (int i = 0; i < 2; i++) cp16(sa[i] + so, aptr[i] + s*32);
                #pragma unroll
                for (int i = 0; i < 4; i++) cp16(sbb[i] + so, bptr[i] + s*32);
                CP_COMMIT();
            }

            float acc[2][4][4];
            #pragma unroll
            for (int mt = 0; mt < 2; mt++)
                #pragma unroll
                for (int nt = 0; nt < 4; nt++)
                    #pragma unroll
                    for (int q = 0; q < 4; q++) acc[mt][nt][q] = 0.f;

            for (int s = 0; s < NS; s++) {
                CP_WAIT2();
                __syncthreads();
                int slot = s % 3;
                mma_stage64((const uint32_t*)smem + slot*STAGE_F, wm, wn, gid, tig, acc);
                __syncthreads();
                if (s + 3 < NS) {
                    uint32_t so = slot*STAGE_F*4;
                    #pragma unroll
                    for (int i = 0; i < 2; i++) cp16(sa[i] + so, aptr[i] + (s + 3)*32);
                    #pragma unroll
                    for (int i = 0; i < 4; i++) cp16(sbb[i] + so, bptr[i] + (s + 3)*32);
                }
                CP_COMMIT();
            }

            #pragma unroll
            for (int mt = 0; mt < 2; mt++) {
                #pragma unroll
                for (int half = 0; half < 2; half++) {
                    int lr = wm*32 + mt*16 + gid + half*8;
                    int row = rows_sh[lr];
                    if (row < 0) continue;
                    float* dst = g_pre + (size_t)row*GDIM + jout*768 + nbase;
                    #pragma unroll
                    for (int nt = 0; nt < 4; nt++) {
                        int n = wn*32 + nt*8 + 2*tig;
                        atomicAdd(&dst[n],   acc[mt][nt][half*2 + 0]);
                        atomicAdd(&dst[n+1], acc[mt][nt][half*2 + 1]);
                    }
                }
            }
        }
    }
}

// ---------------- fused gate + attention + logits seq-part ----------------
__global__ __launch_bounds__(256) void k_attn2(const float* __restrict__ seq,
                                               const float* __restrict__ Wcls,
                                               const float* __restrict__ bcls,
                                               float* __restrict__ out) {
    extern __shared__ float sm[];
    float* sseq = sm;
    float* cbuf = sm + DIM;
    __shared__ float sc[NJ], swt[NJ];
    int m = blockIdx.x, t = threadIdx.x;
    int wid = t >> 5, lane = t & 31;
    unsigned mask = g_amask[m];
    for (int d = t; d < DIM; d += 256) sseq[d] = seq[(size_t)m*DIM + d];
    if (t < NJ) sc[t] = 0.f;
    __syncthreads();

    for (int j = wid; j < NJ; j += 8) {
        if (mask & (1u << j)) {
            const float* pre = g_pre + (size_t)m*GDIM + j*768;
            const float* nf  = g_nflat + (size_t)m*GDIM + j*768;
            float part = 0.f;
            for (int d = lane; d < DIM; d += 32) {
                float cv = (1.f / (1.f + expf(-pre[d]))) * nf[d];
                cbuf[j*768 + d] = cv;
                part += cv * sseq[d];
            }
            #pragma unroll
            for (int o = 16; o; o >>= 1) part += __shfl_xor_sync(0xffffffffu, part, o);
            if (lane == 0) sc[j] = part;
        }
    }
    __syncthreads();
    if (t == 0) {
        float mx = sc[0];
        #pragma unroll
        for (int j = 1; j < NJ; j++) mx = fmaxf(mx, sc[j]);
        float sum = 0.f;
        #pragma unroll
        for (int j = 0; j < NJ; j++) { float e = expf(sc[j]-mx); swt[j] = e; sum += e; }
        float inv = 1.f/sum;
        #pragma unroll
        for (int j = 0; j < NJ; j++) swt[j] *= inv;
    }
    __syncthreads();
    for (int d = t; d < DIM; d += 256) {
        float mix = 0.f;
        unsigned m2 = mask;
        while (m2) {
            int j = __ffs(m2) - 1; m2 &= m2 - 1;
            mix += swt[j] * cbuf[j*768 + d];
        }
        g_combined[(size_t)m*2*DIM + d]       = mix;
        g_combined[(size_t)m*2*DIM + DIM + d] = sseq[d];
    }
    // logits seq-part: out[m,l] = seq . Wcls[l, 0:768] + bcls[l]  (tanh part added later)
    if (wid < NUM_LABELS) {
        const float* wr = Wcls + (size_t)wid*2*DIM;
        float p = 0.f;
        for (int d = lane; d < DIM; d += 32) p += sseq[d]*wr[d];
        #pragma unroll
        for (int o = 16; o; o >>= 1) p += __shfl_xor_sync(0xffffffffu, p, o);
        if (lane == 0) out[m*NUM_LABELS + wid] = p + bcls[wid];
    }
}

// ---------------- attn_out GEMM + fused logits tanh-part ----------------
__global__ __launch_bounds__(256) void k_attnout_mma(const float* __restrict__ Wattn,
                                                     const float* __restrict__ battn,
                                                     const float* __restrict__ Wcls,
                                                     float* __restrict__ out) {
    const int KD = 2*DIM;
    int m0 = blockIdx.x * 64;
    int nbase = blockIdx.y * 128;

    extern __shared__ float smem[];
    __shared__ float sWcls[NUM_LABELS][128];
    uint32_t sb = smem_u32(smem);
    int tid = threadIdx.x;
    int wid = tid >> 5, lane = tid & 31;
    int gid = lane >> 2, tig = lane & 3;
    int wm = wid & 1, wn = wid >> 1;

    for (int idx = tid; idx < NUM_LABELS*128; idx += 256) {
        int l = idx >> 7, c = idx & 127;
        sWcls[l][c] = Wcls[(size_t)l*KD + DIM + nbase + c];
    }

    const float* bptr[4];
    uint32_t sbb[4];
    #pragma unroll
    for (int i = 0; i < 4; i++) {
        int idx = i*256 + tid;
        int row = idx >> 3, seg = idx & 7;
        bptr[i] = Wattn + (size_t)(nbase + row)*KD + seg*4;
        sbb[i] = sb + ((64*ROWP) + row*ROWP + seg*4)*4;
    }
    const float* aptr[2];
    uint32_t sa[2];
    #pragma unroll
    for (int i = 0; i < 2; i++) {
        int idx = i*256 + tid;
        int row = idx >> 3, seg = idx & 7;
        aptr[i] = g_combined + (size_t)(m0 + row)*KD + seg*4;
        sa[i] = sb + (row*ROWP + seg*4)*4;
    }

    const int NS = 48;
    #pragma unroll
    for (int s = 0; s < 3; s++) {
        uint32_t so = s*STAGE_F*4;
        #pragma unroll
        for (int i = 0; i < 2; i++) cp16(sa[i] + so, aptr[i] + s*32);
        #pragma unroll
        for (int i = 0; i < 4; i++) cp16(sbb[i] + so, bptr[i] + s*32);
        CP_COMMIT();
    }

    float acc[2][4][4];
    #pragma unroll
    for (int mt = 0; mt < 2; mt++)
        #pragma unroll
        for (int nt = 0; nt < 4; nt++)
            #pragma unroll
            for (int q = 0; q < 4; q++) acc[mt][nt][q] = 0.f;

    for (int s = 0; s < NS; s++) {
        CP_WAIT2();
        __syncthreads();
        int slot = s % 3;
        mma_stage64((const uint32_t*)smem + slot*STAGE_F, wm, wn, gid, tig, acc);
        __syncthreads();
        if (s + 3 < NS) {
            uint32_t so = slot*STAGE_F*4;
            #pragma unroll
            for (int i = 0; i < 2; i++) cp16(sa[i] + so, aptr[i] + (s + 3)*32);
            #pragma unroll
            for (int i = 0; i < 4; i++) cp16(sbb[i] + so, bptr[i] + (s + 3)*32);
        }
        CP_COMMIT();
    }

    #pragma unroll
    for (int mt = 0; mt < 2; mt++) {
        #pragma unroll
        for (int half = 0; half < 2; half++) {
            int m = m0 + wm*32 + mt*16 + gid + half*8;
            float lg[NUM_LABELS];
            #pragma unroll
            for (int l = 0; l < NUM_LABELS; l++) lg[l] = 0.f;
            #pragma unroll
            for (int nt = 0; nt < 4; nt++) {
                int c = wn*32 + nt*8 + 2*tig;
                int n = nbase + c;
                float v0 = tanhf(acc[mt][nt][half*2 + 0] + battn[n]);
                float v1 = tanhf(acc[mt][nt][half*2 + 1] + battn[n+1]);
                #pragma unroll
                for (int l = 0; l < NUM_LABELS; l++)
                    lg[l] += v0*sWcls[l][c] + v1*sWcls[l][c+1];
            }
            #pragma unroll
            for (int l = 0; l < NUM_LABELS; l++)
                atomicAdd(&out[m*NUM_LABELS + l], lg[l]);
        }
    }
}

// ---------------- launch ----------------
extern "C" void kernel_launch(void* const* d_in, const int* in_sizes, int n_in,
                              void* d_out, int out_size) {
    const float* seq   = (const float*)d_in[0];
    const int*   ids   = (const int*)  d_in[1];
    const int*   nb    = (const int*)  d_in[2];
    const float* Wmlp  = (const float*)d_in[3];
    const float* bmlp  = (const float*)d_in[4];
    const float* Wattn = (const float*)d_in[5];
    const float* battn = (const float*)d_in[6];
    const float* Wcls  = (const float*)d_in[7];
    const float* bcls  = (const float*)d_in[8];
    float* out = (float*)d_out;

    cudaFuncSetAttribute(k_gemmU2,      cudaFuncAttributeMaxDynamicSharedMemorySize, SMEM_U_BYTES);
    cudaFuncSetAttribute(k_attnout_mma, cudaFuncAttributeMaxDynamicSharedMemorySize, SMEM_U_BYTES);

    k_init<<<(V+255)/256, 256>>>();
    k_scatter2<<<2, SLEN>>>(ids);
    k_emb_all<<<M_TOK*NJ, 192>>>(nb, seq, bmlp);
    k_pairs2<<<NPAIR, 256>>>();
    dim3 gu(3, 6, NPAIR);
    k_gemmU2<<<gu, 256, SMEM_U_BYTES>>>(seq, Wmlp);
    int attn_smem = (DIM + NJ*DIM)*4;
    k_attn2<<<M_TOK, 256, attn_smem>>>(seq, Wcls, bcls, out);
    dim3 go(M_TOK/64, 6);
    k_attnout_mma<<<go, 256, SMEM_U_BYTES>>>(Wattn, battn, Wcls, out);
}